// round 1
// baseline (speedup 1.0000x reference)
#include <cuda_runtime.h>
#include <cstdint>

// FeatureSim: attn[b,i,j] = softmax_j( masked(-sum_f |x[b,i,f]-x[b,j,f]| * w[f]) )
// B=8, N=1024, D=64, NUM_FEAT=11, mask: s<1.0 ? -s : 0 ; invalid j -> -1e9
#define BDIM 256

static constexpr int B_ = 8;
static constexpr int N_ = 1024;
static constexpr int D_ = 64;
static constexpr int NF = 11;

__global__ __launch_bounds__(BDIM) void featuresim_kernel(
    const float* __restrict__ x,        // (B,N,D)
    const int*   __restrict__ xlen,     // (B,)
    const float* __restrict__ fimp,     // (NF,)
    float*       __restrict__ out)      // (B,N,N)
{
    const int i = blockIdx.x;   // row
    const int b = blockIdx.y;   // batch
    const int tid = threadIdx.x;
    const int lane = tid & 31;
    const int wid  = tid >> 5;

    __shared__ float sxf[N_ * NF];      // 45056 bytes
    __shared__ float redA[8];
    __shared__ float redB[8];
    __shared__ float s_fi[NF];

    if (tid < NF) s_fi[tid] = fimp[tid];

    // Stage the 11 used features of all 1024 rows of batch b into shared.
    // 16 threads per row; lanes 0..10 active -> mostly-coalesced 44B reads.
    const float* xb = x + (size_t)b * N_ * D_;
    for (int t = tid; t < N_ * 16; t += BDIM) {
        int j = t >> 4;
        int f = t & 15;
        if (f < NF) sxf[j * NF + f] = xb[j * D_ + f];
    }
    __syncthreads();

    const int len = xlen[b];

    float xi[NF], w[NF];
#pragma unroll
    for (int f = 0; f < NF; f++) {
        xi[f] = sxf[i * NF + f];   // broadcast read
        w[f]  = s_fi[f];
    }

    // Each thread: 4 contiguous j values, kept in registers.
    const int j0 = tid * 4;
    float v[4];
#pragma unroll
    for (int q = 0; q < 4; q++) {
        const int j = j0 + q;
        float s = 0.0f;
#pragma unroll
        for (int f = 0; f < NF; f++)
            s = fmaf(fabsf(xi[f] - sxf[j * NF + f]), w[f], s);
        float val = (s < 1.0f) ? -s : 0.0f;
        v[q] = (j < len) ? val : -1.0e9f;
    }

    // ---- block max reduce ----
    float m = fmaxf(fmaxf(v[0], v[1]), fmaxf(v[2], v[3]));
#pragma unroll
    for (int o = 16; o > 0; o >>= 1)
        m = fmaxf(m, __shfl_xor_sync(0xFFFFFFFFu, m, o));
    if (lane == 0) redA[wid] = m;
    __syncthreads();
    m = redA[0];
#pragma unroll
    for (int k = 1; k < 8; k++) m = fmaxf(m, redA[k]);

    // ---- exp + block sum reduce ----
    float e[4];
    float psum = 0.0f;
#pragma unroll
    for (int q = 0; q < 4; q++) {
        e[q] = __expf(v[q] - m);   // underflows to 0 for invalid j
        psum += e[q];
    }
#pragma unroll
    for (int o = 16; o > 0; o >>= 1)
        psum += __shfl_xor_sync(0xFFFFFFFFu, psum, o);
    if (lane == 0) redB[wid] = psum;
    __syncthreads();
    float total = redB[0];
#pragma unroll
    for (int k = 1; k < 8; k++) total += redB[k];

    const float inv = 1.0f / total;

    float4 o4;
    o4.x = e[0] * inv;
    o4.y = e[1] * inv;
    o4.z = e[2] * inv;
    o4.w = e[3] * inv;
    float4* orow = (float4*)(out + ((size_t)b * N_ + i) * N_);
    orow[tid] = o4;
}

extern "C" void kernel_launch(void* const* d_in, const int* in_sizes, int n_in,
                              void* d_out, int out_size)
{
    const float* x    = (const float*)d_in[0];
    const int*   xlen = (const int*)d_in[1];
    const float* fimp = (const float*)d_in[2];
    float*       out  = (float*)d_out;

    dim3 grid(N_, B_);
    featuresim_kernel<<<grid, BDIM>>>(x, xlen, fimp, out);
}

// round 2
// speedup vs baseline: 2.6648x; 2.6648x over previous
#include <cuda_runtime.h>
#include <cstdint>

// FeatureSim: attn[b,i,j] = softmax_j( masked(-sum_f |x[b,i,f]-x[b,j,f]| * w[f]) )
// B=8, N=1024, D=64, NF=11.  Two kernels:
//   1) compact x[:,:,:11] -> dense (B,N,12) scratch (L1-resident working set, 48KB/batch)
//   2) main: R=4 rows per CTA, j-rows register-cached, fma-bound inner loop.

static constexpr int B_ = 8;
static constexpr int N_ = 1024;
static constexpr int D_ = 64;
static constexpr int NF = 11;
static constexpr int RPAD = 12;   // padded row: 3 x float4
static constexpr int R = 4;       // output rows per CTA
#define BDIM 256

__device__ float g_xc[B_ * N_ * RPAD];   // 384 KB scratch

__global__ void compact_kernel(const float* __restrict__ x) {
    int idx = blockIdx.x * blockDim.x + threadIdx.x;     // 0 .. B*N*3
    if (idx >= B_ * N_ * 3) return;
    int row = idx / 3;
    int q   = idx - row * 3;
    float4 v = *reinterpret_cast<const float4*>(x + (size_t)row * D_ + q * 4);
    *reinterpret_cast<float4*>(g_xc + row * RPAD + q * 4) = v;
}

__global__ __launch_bounds__(BDIM) void featuresim_kernel(
    const int*   __restrict__ xlen,     // (B,)
    const float* __restrict__ fimp,     // (NF,)
    float*       __restrict__ out)      // (B,N,N)
{
    const int b   = blockIdx.y;
    const int i0  = blockIdx.x * R;
    const int tid = threadIdx.x;
    const int lane = tid & 31;
    const int wid  = tid >> 5;

    const float* xcb = g_xc + b * N_ * RPAD;
    const int len = xlen[b];

    float w[NF];
#pragma unroll
    for (int f = 0; f < NF; f++) w[f] = __ldg(fimp + f);

    // Register-cache this thread's 4 j-rows (12 x LDG.128, 192B contiguous).
    const int j0 = tid * 4;
    float4 rowv[4][3];
#pragma unroll
    for (int q = 0; q < 4; q++)
#pragma unroll
        for (int g = 0; g < 3; g++)
            rowv[q][g] = *reinterpret_cast<const float4*>(xcb + (j0 + q) * RPAD + g * 4);

    float v[R][4];
#pragma unroll
    for (int r = 0; r < R; r++) {
        float xi[NF];
#pragma unroll
        for (int f = 0; f < NF; f++) xi[f] = xcb[(i0 + r) * RPAD + f];   // broadcast L1 hits

        float s0 = 0.f, s1 = 0.f, s2 = 0.f, s3 = 0.f;
#pragma unroll
        for (int f = 0; f < NF; f++) {
            const float xif = xi[f];
            const float wf  = w[f];
            const float* r0 = reinterpret_cast<const float*>(rowv[0]);
            const float* r1 = reinterpret_cast<const float*>(rowv[1]);
            const float* r2 = reinterpret_cast<const float*>(rowv[2]);
            const float* r3 = reinterpret_cast<const float*>(rowv[3]);
            s0 = fmaf(fabsf(r0[f] - xif), wf, s0);
            s1 = fmaf(fabsf(r1[f] - xif), wf, s1);
            s2 = fmaf(fabsf(r2[f] - xif), wf, s2);
            s3 = fmaf(fabsf(r3[f] - xif), wf, s3);
        }
        float t0 = (s0 < 1.0f) ? -s0 : 0.0f;
        float t1 = (s1 < 1.0f) ? -s1 : 0.0f;
        float t2 = (s2 < 1.0f) ? -s2 : 0.0f;
        float t3 = (s3 < 1.0f) ? -s3 : 0.0f;
        v[r][0] = (j0 + 0 < len) ? t0 : -1.0e9f;
        v[r][1] = (j0 + 1 < len) ? t1 : -1.0e9f;
        v[r][2] = (j0 + 2 < len) ? t2 : -1.0e9f;
        v[r][3] = (j0 + 3 < len) ? t3 : -1.0e9f;
    }

    __shared__ float redm[R][8];
    __shared__ float reds[R][8];

    // ---- block max per row ----
#pragma unroll
    for (int r = 0; r < R; r++) {
        float mm = fmaxf(fmaxf(v[r][0], v[r][1]), fmaxf(v[r][2], v[r][3]));
#pragma unroll
        for (int o = 16; o > 0; o >>= 1)
            mm = fmaxf(mm, __shfl_xor_sync(0xFFFFFFFFu, mm, o));
        if (lane == 0) redm[r][wid] = mm;
    }
    __syncthreads();

    float m[R];
#pragma unroll
    for (int r = 0; r < R; r++) {
        float mm = redm[r][0];
#pragma unroll
        for (int k = 1; k < 8; k++) mm = fmaxf(mm, redm[r][k]);
        m[r] = mm;
    }

    // ---- exp + block sum per row ----
#pragma unroll
    for (int r = 0; r < R; r++) {
        float ps = 0.0f;
#pragma unroll
        for (int q = 0; q < 4; q++) {
            v[r][q] = __expf(v[r][q] - m[r]);   // invalid j underflows to exactly 0
            ps += v[r][q];
        }
#pragma unroll
        for (int o = 16; o > 0; o >>= 1)
            ps += __shfl_xor_sync(0xFFFFFFFFu, ps, o);
        if (lane == 0) reds[r][wid] = ps;
    }
    __syncthreads();

#pragma unroll
    for (int r = 0; r < R; r++) {
        float t = reds[r][0];
#pragma unroll
        for (int k = 1; k < 8; k++) t += reds[r][k];
        const float inv = 1.0f / t;
        float4 o4;
        o4.x = v[r][0] * inv;
        o4.y = v[r][1] * inv;
        o4.z = v[r][2] * inv;
        o4.w = v[r][3] * inv;
        *reinterpret_cast<float4*>(out + ((size_t)(b * N_ + i0 + r)) * N_ + j0) = o4;
    }
}

extern "C" void kernel_launch(void* const* d_in, const int* in_sizes, int n_in,
                              void* d_out, int out_size)
{
    const float* x    = (const float*)d_in[0];
    const int*   xlen = (const int*)d_in[1];
    const float* fimp = (const float*)d_in[2];
    float*       out  = (float*)d_out;

    compact_kernel<<<(B_ * N_ * 3 + BDIM - 1) / BDIM, BDIM>>>(x);
    dim3 grid(N_ / R, B_);
    featuresim_kernel<<<grid, BDIM>>>(xlen, fimp, out);
}